// round 16
// baseline (speedup 1.0000x reference)
#include <cuda_runtime.h>
#include <cuda_fp16.h>
#include <cstdint>
#include <math.h>

#define D_MODEL 768
#define NH 12
#define HD 64
#define BATCH 4
#define SEQ 2048
#define MTOT (BATCH*SEQ)   // 8192

// ---------------- scratch (static __device__: allocation-free) ----------------
__device__ __half g_x[MTOT * D_MODEL];
__device__ __half g_w[4 * D_MODEL * D_MODEL];
__device__ __half g_q[MTOT * D_MODEL];
__device__ __half g_k[MTOT * D_MODEL];
__device__ __half g_v[MTOT * D_MODEL];
__device__ __half g_a[MTOT * D_MODEL];

// ---------------- helpers ----------------
__device__ __forceinline__ uint32_t smem_u32(const void* p) {
    uint32_t a;
    asm("{ .reg .u64 t; cvta.to.shared.u64 t, %1; cvt.u32.u64 %0, t; }" : "=r"(a) : "l"(p));
    return a;
}
#define CP16(dst, src) \
    asm volatile("cp.async.cg.shared.global [%0], [%1], 16;" :: "r"(dst), "l"(src))
#define CP_COMMIT() asm volatile("cp.async.commit_group;" ::: "memory")
#define CP_WAIT(n)  asm volatile("cp.async.wait_group %0;" :: "n"(n) : "memory")

__device__ __forceinline__ void ldmx4(uint32_t addr, uint32_t& r0, uint32_t& r1,
                                      uint32_t& r2, uint32_t& r3) {
    asm volatile("ldmatrix.sync.aligned.m8n8.x4.shared.b16 {%0,%1,%2,%3}, [%4];"
                 : "=r"(r0), "=r"(r1), "=r"(r2), "=r"(r3) : "r"(addr));
}
__device__ __forceinline__ void ldmx4t(uint32_t addr, uint32_t& r0, uint32_t& r1,
                                       uint32_t& r2, uint32_t& r3) {
    asm volatile("ldmatrix.sync.aligned.m8n8.x4.trans.shared.b16 {%0,%1,%2,%3}, [%4];"
                 : "=r"(r0), "=r"(r1), "=r"(r2), "=r"(r3) : "r"(addr));
}
// fp32-accumulate HMMA
__device__ __forceinline__ void mma_f16(float* c, const uint32_t* a, const uint32_t* b) {
    asm volatile("mma.sync.aligned.m16n8k16.row.col.f32.f16.f16.f32 "
                 "{%0,%1,%2,%3}, {%4,%5,%6,%7}, {%8,%9}, {%0,%1,%2,%3};"
                 : "+f"(c[0]), "+f"(c[1]), "+f"(c[2]), "+f"(c[3])
                 : "r"(a[0]), "r"(a[1]), "r"(a[2]), "r"(a[3]), "r"(b[0]), "r"(b[1]));
}
// fp16-accumulate HMMA (packed fp16 output — kills converts in softmax path)
__device__ __forceinline__ void mma_f16acc(uint32_t* d, const uint32_t* a, const uint32_t* b) {
    asm volatile("mma.sync.aligned.m16n8k16.row.col.f16.f16.f16.f16 "
                 "{%0,%1}, {%2,%3,%4,%5}, {%6,%7}, {%0,%1};"
                 : "+r"(d[0]), "+r"(d[1])
                 : "r"(a[0]), "r"(a[1]), "r"(a[2]), "r"(a[3]), "r"(b[0]), "r"(b[1]));
}

// ---------------- merged prep: one launch, exact-sized 1D grid ----------------
#define NX2 (MTOT * D_MODEL / 2)
#define NW2 (D_MODEL * D_MODEL / 2)
#define BLK_X ((NX2 + 255) / 256)
#define BLK_W ((NW2 + 255) / 256)
#define PREP_BLOCKS (BLK_X + 4 * BLK_W)

__global__ void prep_all(const float2* __restrict__ x,
                         const float2* __restrict__ w0, const float2* __restrict__ w1,
                         const float2* __restrict__ w2, const float2* __restrict__ w3,
                         __half2* __restrict__ xo, __half2* __restrict__ wo)
{
    int bid = blockIdx.x;
    if (bid < BLK_X) {
        int i = bid * 256 + threadIdx.x;
        if (i < NX2) {
            float2 v = x[i];
            xo[i] = __floats2half2_rn(v.x, v.y);
        }
    } else {
        int r = bid - BLK_X;
        int z = r / BLK_W;
        int i = (r % BLK_W) * 256 + threadIdx.x;
        if (i < NW2) {
            const float2* src = (z == 0) ? w0 : (z == 1) ? w1 : (z == 2) ? w2 : w3;
            float sc = (z == 0) ? 0.125f * 1.4426950408889634f : 1.0f;
            float2 v = src[i];
            wo[(size_t)z * NW2 + i] = __floats2half2_rn(v.x * sc, v.y * sc);
        }
    }
}

// ---------------------------------------------------------------------------
// QKV GEMM: single-pass fp16 NT, BM=128, BN=128, BK=64, 2-stage (unchanged).
// ---------------------------------------------------------------------------
#define BM 128
#define BN 128
#define BK 64
#define NCHUNK (D_MODEL / BK)            // 12
#define ROWH 72
#define TBYTES (BM * ROWH * 2)           // 18432
#define STB (2 * TBYTES)                 // 36864
#define GSMEM (2 * STB)                  // 73728

__global__ void __launch_bounds__(256, 2)
gemm_qkv(const __half* __restrict__ Ain, const __half* __restrict__ W,
         __half* __restrict__ Qo, __half* __restrict__ Ko, __half* __restrict__ Vo)
{
    extern __shared__ char smem[];
    const uint32_t sb = smem_u32(smem);
    const int tid  = threadIdx.x;
    const int wid  = tid >> 5;
    const int lane = tid & 31;
    const int warp_m = wid & 1;
    const int warp_n = wid >> 1;
    const int z = blockIdx.z;

    const int m0 = blockIdx.y * BM;
    const int n0 = blockIdx.x * BN;
    const int K  = D_MODEL;
    const __half* B = W + (size_t)z * D_MODEL * D_MODEL;

    auto load_chunk = [&](int k0, int stage) {
        const uint32_t sbase = sb + stage * STB;
#pragma unroll
        for (int j = 0; j < 4; j++) {
            int u   = tid + j * 256;
            int row = u >> 3;
            int ch  = u & 7;
            uint32_t so = (uint32_t)((row * ROWH + ch * 8) * 2);
            size_t ga = (size_t)(m0 + row) * K + k0 + ch * 8;
            size_t gb = (size_t)(n0 + row) * K + k0 + ch * 8;
            CP16(sbase + so,          Ain + ga);
            CP16(sbase + TBYTES + so, B   + gb);
        }
        CP_COMMIT();
    };

    float acc[4][4][4];
#pragma unroll
    for (int i = 0; i < 4; i++)
#pragma unroll
        for (int j = 0; j < 4; j++)
#pragma unroll
            for (int r = 0; r < 4; r++) acc[i][j][r] = 0.0f;

    load_chunk(0, 0);

    const uint32_t a_off = (uint32_t)(((warp_m * 64 + (lane & 15)) * ROWH + (lane >> 4) * 8) * 2);
    const uint32_t kRow  = (uint32_t)((lane & 7) + ((lane >> 4) << 3));
    const uint32_t kHalf = (uint32_t)(((lane >> 3) & 1) * 8);

    for (int c = 0; c < NCHUNK; c++) {
        if (c + 1 < NCHUNK) {
            load_chunk((c + 1) * BK, (c + 1) & 1);
            CP_WAIT(1);
        } else {
            CP_WAIT(0);
        }
        __syncthreads();

        const uint32_t sbase = sb + (c & 1) * STB;
        const uint32_t sA = sbase;
        const uint32_t sB = sbase + TBYTES;

#pragma unroll
        for (int ks = 0; ks < 4; ks++) {
            const uint32_t koff = (uint32_t)(ks * 16 * 2);
            uint32_t aH[4][4], bH[4][2];
#pragma unroll
            for (int mt = 0; mt < 4; mt++) {
                uint32_t ao = a_off + koff + (uint32_t)(mt * 16 * ROWH * 2);
                ldmx4(sA + ao, aH[mt][0], aH[mt][1], aH[mt][2], aH[mt][3]);
            }
#pragma unroll
            for (int ntp = 0; ntp < 2; ntp++) {
                uint32_t bo = (uint32_t)(((warp_n * 32 + ntp * 16 + kRow) * ROWH + ks * 16 + kHalf) * 2);
                ldmx4(sB + bo, bH[2 * ntp][0], bH[2 * ntp][1],
                               bH[2 * ntp + 1][0], bH[2 * ntp + 1][1]);
            }
#pragma unroll
            for (int mt = 0; mt < 4; mt++)
#pragma unroll
                for (int nt = 0; nt < 4; nt++)
                    mma_f16(acc[mt][nt], aH[mt], bH[nt]);
        }
        __syncthreads();
    }

    const int mb = m0 + warp_m * 64;
    const int nb = n0 + warp_n * 32;
    __half* dst = (z == 0) ? Qo : (z == 1) ? Ko : Vo;
#pragma unroll
    for (int mt = 0; mt < 4; mt++) {
#pragma unroll
        for (int nt = 0; nt < 4; nt++) {
            int r0 = mb + mt * 16 + (lane >> 2);
            int c0 = nb + nt * 8 + (lane & 3) * 2;
            *(__half2*)(dst + (size_t)r0 * D_MODEL + c0) =
                __floats2half2_rn(acc[mt][nt][0], acc[mt][nt][1]);
            *(__half2*)(dst + (size_t)(r0 + 8) * D_MODEL + c0) =
                __floats2half2_rn(acc[mt][nt][2], acc[mt][nt][3]);
        }
    }
}

// ---------------------------------------------------------------------------
// O-projection GEMM: BM=64, BN=128, 128 threads, 4 warps (warp tile 32x64),
// 4 CTAs/SM -> grid 768 CTAs: halves per-CTA time, shrinks the wave tail.
// Same K-chunk order as before -> bit-identical accumulation.
// ---------------------------------------------------------------------------
#define OBM 64
#define OATB (OBM * ROWH * 2)            // 9216 (A tile)
#define OSTB (OATB + TBYTES)             // 27648 per stage
#define OSMEM (2 * OSTB)                 // 55296

__global__ void __launch_bounds__(128, 4)
gemm_o(const __half* __restrict__ Ain, const __half* __restrict__ W,
       float* __restrict__ F)
{
    extern __shared__ char smem[];
    const uint32_t sb = smem_u32(smem);
    const int tid  = threadIdx.x;
    const int wid  = tid >> 5;          // 0..3
    const int lane = tid & 31;
    const int warp_m = wid & 1;         // 2 x 32 rows
    const int warp_n = wid >> 1;        // 2 x 64 cols

    const int m0 = blockIdx.y * OBM;
    const int n0 = blockIdx.x * BN;
    const int K  = D_MODEL;

    auto load_chunk = [&](int k0, int stage) {
        const uint32_t sbase = sb + stage * OSTB;
#pragma unroll
        for (int j = 0; j < 4; j++) {           // A: 64 rows x 8 ch = 512
            int u   = tid + j * 128;
            int row = u >> 3;
            int ch  = u & 7;
            uint32_t so = (uint32_t)((row * ROWH + ch * 8) * 2);
            CP16(sbase + so, Ain + (size_t)(m0 + row) * K + k0 + ch * 8);
        }
#pragma unroll
        for (int j = 0; j < 8; j++) {           // B: 128 rows x 8 ch = 1024
            int u   = tid + j * 128;
            int row = u >> 3;
            int ch  = u & 7;
            uint32_t so = (uint32_t)((row * ROWH + ch * 8) * 2);
            CP16(sbase + OATB + so, W + (size_t)(n0 + row) * K + k0 + ch * 8);
        }
        CP_COMMIT();
    };

    float acc[2][8][4];
#pragma unroll
    for (int i = 0; i < 2; i++)
#pragma unroll
        for (int j = 0; j < 8; j++)
#pragma unroll
            for (int r = 0; r < 4; r++) acc[i][j][r] = 0.0f;

    load_chunk(0, 0);

    const uint32_t a_off = (uint32_t)(((warp_m * 32 + (lane & 15)) * ROWH + (lane >> 4) * 8) * 2);
    const uint32_t kRow  = (uint32_t)((lane & 7) + ((lane >> 4) << 3));
    const uint32_t kHalf = (uint32_t)(((lane >> 3) & 1) * 8);

    for (int c = 0; c < NCHUNK; c++) {
        if (c + 1 < NCHUNK) {
            load_chunk((c + 1) * BK, (c + 1) & 1);
            CP_WAIT(1);
        } else {
            CP_WAIT(0);
        }
        __syncthreads();

        const uint32_t sbase = sb + (c & 1) * OSTB;
        const uint32_t sA = sbase;
        const uint32_t sB = sbase + OATB;

#pragma unroll
        for (int ks = 0; ks < 4; ks++) {
            const uint32_t koff = (uint32_t)(ks * 16 * 2);
            uint32_t aH[2][4], bH[8][2];
#pragma unroll
            for (int mt = 0; mt < 2; mt++) {
                uint32_t ao = a_off + koff + (uint32_t)(mt * 16 * ROWH * 2);
                ldmx4(sA + ao, aH[mt][0], aH[mt][1], aH[mt][2], aH[mt][3]);
            }
#pragma unroll
            for (int ntp = 0; ntp < 4; ntp++) {
                uint32_t bo = (uint32_t)(((warp_n * 64 + ntp * 16 + kRow) * ROWH + ks * 16 + kHalf) * 2);
                ldmx4(sB + bo, bH[2 * ntp][0], bH[2 * ntp][1],
                               bH[2 * ntp + 1][0], bH[2 * ntp + 1][1]);
            }
#pragma unroll
            for (int mt = 0; mt < 2; mt++)
#pragma unroll
                for (int nt = 0; nt < 8; nt++)
                    mma_f16(acc[mt][nt], aH[mt], bH[nt]);
        }
        __syncthreads();
    }

    const int mb = m0 + warp_m * 32;
    const int nb = n0 + warp_n * 64;
#pragma unroll
    for (int mt = 0; mt < 2; mt++) {
#pragma unroll
        for (int nt = 0; nt < 8; nt++) {
            int r0 = mb + mt * 16 + (lane >> 2);
            int c0 = nb + nt * 8 + (lane & 3) * 2;
            *(float2*)(F + (size_t)r0 * D_MODEL + c0) =
                make_float2(acc[mt][nt][0], acc[mt][nt][1]);
            *(float2*)(F + (size_t)(r0 + 8) * D_MODEL + c0) =
                make_float2(acc[mt][nt][2], acc[mt][nt][3]);
        }
    }
}

// ---------------------------------------------------------------------------
// fp16 flash attention (causal), max-free exp2 softmax, f16-acc S.
// Diagonal-tile block skip — S blocks / P column-groups entirely above the
// causal boundary are exactly zero post-mask; their MMAs are skipped
// (contributes exactly 0, bit-identical output).
// ---------------------------------------------------------------------------
#define QT_B  (64 * 72 * 2)              // 9216
#define KVT_B (64 * 72 * 2)              // 9216
#define AT_SMEM (QT_B + 4 * KVT_B)       // 46080

__global__ void __launch_bounds__(128, 4)
attn3(const __half* __restrict__ Qp, const __half* __restrict__ Kp,
      const __half* __restrict__ Vp, __half* __restrict__ Oo)
{
    extern __shared__ char smem[];
    const uint32_t sb = smem_u32(smem);
    const int tid  = threadIdx.x;
    const int wid  = tid >> 5;         // 0..3
    const int lane = tid & 31;

    const int qt = (SEQ / 64 - 1) - blockIdx.x;   // descending
    const int h  = blockIdx.y;
    const int b  = blockIdx.z;
    const int q0 = qt * 64;
    const int ktmax = qt;

    const size_t gbase = ((size_t)b * SEQ) * D_MODEL + h * HD;

    // ---- load Q (own commit group) ----
#pragma unroll
    for (int j = 0; j < 4; j++) {
        int u = tid + j * 128;
        int row = u >> 3, ch = u & 7;
        uint32_t dst = sb + (uint32_t)((row * 72 + ch * 8) * 2);
        CP16(dst, Qp + gbase + (size_t)(q0 + row) * D_MODEL + ch * 8);
    }
    CP_COMMIT();

    const uint32_t kvbase = sb + QT_B;
    auto load_kv = [&](int kt, int stage) {
        const int k0 = kt * 64;
        const uint32_t sbase = kvbase + stage * 2 * KVT_B;
        const __half* src[2] = { Kp, Vp };
#pragma unroll
        for (int a = 0; a < 2; a++)
#pragma unroll
            for (int j = 0; j < 4; j++) {
                int u = tid + j * 128;
                int row = u >> 3, ch = u & 7;
                uint32_t dst = sbase + a * KVT_B + (uint32_t)((row * 72 + ch * 8) * 2);
                CP16(dst, src[a] + gbase + (size_t)(k0 + row) * D_MODEL + ch * 8);
            }
        CP_COMMIT();
    };

    load_kv(0, 0);
    if (ktmax >= 1) load_kv(1, 1);

    // ---- wait for Q, hoist Q fragments ----
    if (ktmax >= 1) { CP_WAIT(2); } else { CP_WAIT(1); }
    __syncthreads();
    uint32_t qh[4][4];
    {
        const uint32_t a_off = (uint32_t)(((wid * 16 + (lane & 15)) * 72 + (lane >> 4) * 8) * 2);
#pragma unroll
        for (int kc = 0; kc < 4; kc++) {
            uint32_t ao = a_off + (uint32_t)(kc * 16 * 2);
            ldmx4(sb + ao, qh[kc][0], qh[kc][1], qh[kc][2], qh[kc][3]);
        }
    }

    float l0 = 0.0f, l1 = 0.0f;
    float o[8][4];
#pragma unroll
    for (int nt = 0; nt < 8; nt++)
#pragma unroll
        for (int r = 0; r < 4; r++) o[nt][r] = 0.0f;

    const int rbase = q0 + wid * 16 + (lane >> 2);
    const int rmax  = q0 + wid * 16 + 15;
    const __half2 row0h = __float2half2_rn((float)rbase);
    const __half2 row1h = __float2half2_rn((float)(rbase + 8));

    for (int kt = 0; kt <= ktmax; kt++) {
        if (kt + 1 <= ktmax) { CP_WAIT(1); } else { CP_WAIT(0); }
        __syncthreads();

        const int k0 = kt * 64;
        // highest 16-col block index with any unmasked column for this warp
        const int ntop = (rmax - k0) >> 4;       // may be >3 (full) or <0 (inactive)

        if (ntop >= 0) {
            const int nhi = ntop > 3 ? 3 : ntop; // blocks ntp<=nhi have live columns
            const uint32_t skv = kvbase + (kt & 1) * 2 * KVT_B;
            const uint32_t sK = skv, sV = skv + KVT_B;

            // ---- S = Q K^T, fp16 accumulate; skip fully-masked blocks ----
            uint32_t sh[8][2];
#pragma unroll
            for (int nt = 0; nt < 8; nt++) { sh[nt][0] = 0u; sh[nt][1] = 0u; }

            const uint32_t kRow = (uint32_t)((lane & 7) + ((lane >> 4) << 3));
            const uint32_t kHalf = (uint32_t)(((lane >> 3) & 1) * 8);
#pragma unroll
            for (int kc = 0; kc < 4; kc++) {
#pragma unroll
                for (int ntp = 0; ntp < 4; ntp++) {
                    if (ntp > nhi) break;
                    uint32_t off = (uint32_t)(((ntp * 16 + kRow) * 72 + kc * 16 + kHalf) * 2);
                    uint32_t h0, h1, h2, h3;
                    ldmx4(sK + off, h0, h1, h2, h3);
                    uint32_t bHe[2] = { h0, h1 }, bHo[2] = { h2, h3 };
                    mma_f16acc(sh[2 * ntp],     qh[kc], bHe);
                    mma_f16acc(sh[2 * ntp + 1], qh[kc], bHo);
                }
            }

            // ---- P = exp2(S) ----
            __half2 e[8][2];
#pragma unroll
            for (int nt = 0; nt < 8; nt++) {
                e[nt][0] = h2exp2(*(__half2*)&sh[nt][0]);
                e[nt][1] = h2exp2(*(__half2*)&sh[nt][1]);
            }

            // ---- causal mask (zeroes partial AND skipped blocks) ----
            if (k0 + 63 > q0 + wid * 16) {
                const int cb = k0 + (lane & 3) * 2;
#pragma unroll
                for (int nt = 0; nt < 8; nt++) {
                    float c0 = (float)(cb + nt * 8);
                    __half2 colh = __floats2half2_rn(c0, c0 + 1.0f);
                    e[nt][0] = __hmul2(e[nt][0], __hle2(colh, row0h));
                    e[nt][1] = __hmul2(e[nt][1], __hle2(colh, row1h));
                }
            }

            // ---- row sums ----
            {
                __half2 t0 = __hadd2(__hadd2(__hadd2(e[0][0], e[1][0]), __hadd2(e[2][0], e[3][0])),
                                     __hadd2(__hadd2(e[4][0], e[5][0]), __hadd2(e[6][0], e[7][0])));
                __half2 t1 = __hadd2(__hadd2(__hadd2(e[0][1], e[1][1]), __hadd2(e[2][1], e[3][1])),
                                     __hadd2(__hadd2(e[4][1], e[5][1]), __hadd2(e[6][1], e[7][1])));
                float2 f0 = __half22float2(t0), f1 = __half22float2(t1);
                l0 += f0.x + f0.y;
                l1 += f1.x + f1.y;
            }

            // ---- O += P V; skip all-zero P column groups (exactly 0) ----
            const uint32_t vKey = (uint32_t)((lane & 7) + (((lane >> 3) & 1) << 3));
            const uint32_t vDimSel = (uint32_t)((lane >> 4) * 8);
#pragma unroll
            for (int kc = 0; kc < 4; kc++) {
                if (kc > nhi) break;
                uint32_t pa[4] = { *(uint32_t*)&e[2 * kc][0], *(uint32_t*)&e[2 * kc][1],
                                   *(uint32_t*)&e[2 * kc + 1][0], *(uint32_t*)&e[2 * kc + 1][1] };
#pragma unroll
                for (int ntp = 0; ntp < 4; ntp++) {
                    uint32_t off = (uint32_t)(((kc * 16 + vKey) * 72 + ntp * 16 + vDimSel) * 2);
                    uint32_t h0, h1, h2, h3;
                    ldmx4t(sV + off, h0, h1, h2, h3);
                    uint32_t bHe[2] = { h0, h1 }, bHo[2] = { h2, h3 };
                    mma_f16(o[2 * ntp],     pa, bHe);
                    mma_f16(o[2 * ntp + 1], pa, bHo);
                }
            }
        }

        __syncthreads();
        if (kt + 2 <= ktmax) load_kv(kt + 2, kt & 1);
    }

    // ---- epilogue ----
    l0 += __shfl_xor_sync(0xffffffffu, l0, 1);
    l0 += __shfl_xor_sync(0xffffffffu, l0, 2);
    l1 += __shfl_xor_sync(0xffffffffu, l1, 1);
    l1 += __shfl_xor_sync(0xffffffffu, l1, 2);
    const float inv0 = 1.0f / l0, inv1 = 1.0f / l1;
    const size_t orow0 = gbase + (size_t)(q0 + wid * 16 + (lane >> 2)) * D_MODEL + (lane & 3) * 2;
    const size_t orow1 = orow0 + 8 * D_MODEL;
#pragma unroll
    for (int nt = 0; nt < 8; nt++) {
        *(__half2*)(Oo + orow0 + nt * 8) =
            __floats2half2_rn(o[nt][0] * inv0, o[nt][1] * inv0);
        *(__half2*)(Oo + orow1 + nt * 8) =
            __floats2half2_rn(o[nt][2] * inv1, o[nt][3] * inv1);
    }
}

// ---------------------------------------------------------------------------
extern "C" void kernel_launch(void* const* d_in, const int* in_sizes, int n_in,
                              void* d_out, int out_size)
{
    const float* x  = (const float*)d_in[0];
    float* out = (float*)d_out;

    __half *xh, *w, *q, *k, *v, *a;
    cudaGetSymbolAddress((void**)&xh, g_x);
    cudaGetSymbolAddress((void**)&w,  g_w);
    cudaGetSymbolAddress((void**)&q,  g_q);
    cudaGetSymbolAddress((void**)&k,  g_k);
    cudaGetSymbolAddress((void**)&v,  g_v);
    cudaGetSymbolAddress((void**)&a,  g_a);

    prep_all<<<PREP_BLOCKS, 256>>>((const float2*)x,
                                   (const float2*)d_in[1], (const float2*)d_in[2],
                                   (const float2*)d_in[3], (const float2*)d_in[4],
                                   (__half2*)xh, (__half2*)w);

    cudaFuncSetAttribute(gemm_qkv, cudaFuncAttributeMaxDynamicSharedMemorySize, GSMEM);
    dim3 gq(D_MODEL / BN, MTOT / BM, 3);
    gemm_qkv<<<gq, 256, GSMEM>>>(xh, w, q, k, v);

    cudaFuncSetAttribute(attn3, cudaFuncAttributeMaxDynamicSharedMemorySize, AT_SMEM);
    dim3 ga(SEQ / 64, NH, BATCH);
    attn3<<<ga, 128, AT_SMEM>>>(q, k, v, a);

    cudaFuncSetAttribute(gemm_o, cudaFuncAttributeMaxDynamicSharedMemorySize, OSMEM);
    dim3 go(D_MODEL / BN, MTOT / OBM);   // (6, 128) = 768 CTAs
    gemm_o<<<go, 128, OSMEM>>>(a, w + 3 * (size_t)D_MODEL * D_MODEL, out);
}

// round 17
// speedup vs baseline: 1.0716x; 1.0716x over previous
#include <cuda_runtime.h>
#include <cuda_fp16.h>
#include <cstdint>
#include <math.h>

#define D_MODEL 768
#define NH 12
#define HD 64
#define BATCH 4
#define SEQ 2048
#define MTOT (BATCH*SEQ)   // 8192

// ---------------- scratch (static __device__: allocation-free) ----------------
__device__ __half g_x[MTOT * D_MODEL];
__device__ __half g_w[4 * D_MODEL * D_MODEL];
__device__ __half g_q[MTOT * D_MODEL];
__device__ __half g_k[MTOT * D_MODEL];
__device__ __half g_v[MTOT * D_MODEL];
__device__ __half g_a[MTOT * D_MODEL];

// ---------------- helpers ----------------
__device__ __forceinline__ uint32_t smem_u32(const void* p) {
    uint32_t a;
    asm("{ .reg .u64 t; cvta.to.shared.u64 t, %1; cvt.u32.u64 %0, t; }" : "=r"(a) : "l"(p));
    return a;
}
#define CP16(dst, src) \
    asm volatile("cp.async.cg.shared.global [%0], [%1], 16;" :: "r"(dst), "l"(src))
#define CP_COMMIT() asm volatile("cp.async.commit_group;" ::: "memory")
#define CP_WAIT(n)  asm volatile("cp.async.wait_group %0;" :: "n"(n) : "memory")

__device__ __forceinline__ void ldmx4(uint32_t addr, uint32_t& r0, uint32_t& r1,
                                      uint32_t& r2, uint32_t& r3) {
    asm volatile("ldmatrix.sync.aligned.m8n8.x4.shared.b16 {%0,%1,%2,%3}, [%4];"
                 : "=r"(r0), "=r"(r1), "=r"(r2), "=r"(r3) : "r"(addr));
}
__device__ __forceinline__ void ldmx4t(uint32_t addr, uint32_t& r0, uint32_t& r1,
                                       uint32_t& r2, uint32_t& r3) {
    asm volatile("ldmatrix.sync.aligned.m8n8.x4.trans.shared.b16 {%0,%1,%2,%3}, [%4];"
                 : "=r"(r0), "=r"(r1), "=r"(r2), "=r"(r3) : "r"(addr));
}
// fp32-accumulate HMMA
__device__ __forceinline__ void mma_f16(float* c, const uint32_t* a, const uint32_t* b) {
    asm volatile("mma.sync.aligned.m16n8k16.row.col.f32.f16.f16.f32 "
                 "{%0,%1,%2,%3}, {%4,%5,%6,%7}, {%8,%9}, {%0,%1,%2,%3};"
                 : "+f"(c[0]), "+f"(c[1]), "+f"(c[2]), "+f"(c[3])
                 : "r"(a[0]), "r"(a[1]), "r"(a[2]), "r"(a[3]), "r"(b[0]), "r"(b[1]));
}
// fp16-accumulate HMMA (packed fp16 output — kills converts in softmax path)
__device__ __forceinline__ void mma_f16acc(uint32_t* d, const uint32_t* a, const uint32_t* b) {
    asm volatile("mma.sync.aligned.m16n8k16.row.col.f16.f16.f16.f16 "
                 "{%0,%1}, {%2,%3,%4,%5}, {%6,%7}, {%0,%1};"
                 : "+r"(d[0]), "+r"(d[1])
                 : "r"(a[0]), "r"(a[1]), "r"(a[2]), "r"(a[3]), "r"(b[0]), "r"(b[1]));
}

// ---------------- merged prep: one launch, exact-sized 1D grid ----------------
#define NX2 (MTOT * D_MODEL / 2)
#define NW2 (D_MODEL * D_MODEL / 2)
#define BLK_X ((NX2 + 255) / 256)
#define BLK_W ((NW2 + 255) / 256)
#define PREP_BLOCKS (BLK_X + 4 * BLK_W)

__global__ void prep_all(const float2* __restrict__ x,
                         const float2* __restrict__ w0, const float2* __restrict__ w1,
                         const float2* __restrict__ w2, const float2* __restrict__ w3,
                         __half2* __restrict__ xo, __half2* __restrict__ wo)
{
    int bid = blockIdx.x;
    if (bid < BLK_X) {
        int i = bid * 256 + threadIdx.x;
        if (i < NX2) {
            float2 v = x[i];
            xo[i] = __floats2half2_rn(v.x, v.y);
        }
    } else {
        int r = bid - BLK_X;
        int z = r / BLK_W;
        int i = (r % BLK_W) * 256 + threadIdx.x;
        if (i < NW2) {
            const float2* src = (z == 0) ? w0 : (z == 1) ? w1 : (z == 2) ? w2 : w3;
            // fold 1/sqrt(64) AND log2(e) into Wq (softmax runs in exp2 domain)
            float sc = (z == 0) ? 0.125f * 1.4426950408889634f : 1.0f;
            float2 v = src[i];
            wo[(size_t)z * NW2 + i] = __floats2half2_rn(v.x * sc, v.y * sc);
        }
    }
}

// ---------------------------------------------------------------------------
// fp16 NT GEMM, BK=64, 2-stage. MODE 0: QKV (z selects W + fp16 output).
//                               MODE 1: O-proj, fp32 output.
// ---------------------------------------------------------------------------
#define BM 128
#define BN 128
#define BK 64
#define NCHUNK (D_MODEL / BK)            // 12
#define ROWH 72
#define TBYTES (BM * ROWH * 2)           // 18432
#define STB (2 * TBYTES)                 // 36864
#define GSMEM (2 * STB)                  // 73728

template<int MODE>
__global__ void __launch_bounds__(256, 2)
gemm2(const __half* __restrict__ Ain, const __half* __restrict__ W,
      __half* __restrict__ Qo, __half* __restrict__ Ko, __half* __restrict__ Vo,
      float* __restrict__ F)
{
    extern __shared__ char smem[];
    const uint32_t sb = smem_u32(smem);
    const int tid  = threadIdx.x;
    const int wid  = tid >> 5;
    const int lane = tid & 31;
    const int warp_m = wid & 1;
    const int warp_n = wid >> 1;
    const int z = (MODE == 0) ? blockIdx.z : 0;

    const int m0 = blockIdx.y * BM;
    const int n0 = blockIdx.x * BN;
    const int K  = D_MODEL;
    const __half* B = W + (size_t)z * D_MODEL * D_MODEL;

    auto load_chunk = [&](int k0, int stage) {
        const uint32_t sbase = sb + stage * STB;
#pragma unroll
        for (int j = 0; j < 4; j++) {
            int u   = tid + j * 256;
            int row = u >> 3;
            int ch  = u & 7;
            uint32_t so = (uint32_t)((row * ROWH + ch * 8) * 2);
            size_t ga = (size_t)(m0 + row) * K + k0 + ch * 8;
            size_t gb = (size_t)(n0 + row) * K + k0 + ch * 8;
            CP16(sbase + so,          Ain + ga);
            CP16(sbase + TBYTES + so, B   + gb);
        }
        CP_COMMIT();
    };

    float acc[4][4][4];
#pragma unroll
    for (int i = 0; i < 4; i++)
#pragma unroll
        for (int j = 0; j < 4; j++)
#pragma unroll
            for (int r = 0; r < 4; r++) acc[i][j][r] = 0.0f;

    load_chunk(0, 0);

    const uint32_t a_off = (uint32_t)(((warp_m * 64 + (lane & 15)) * ROWH + (lane >> 4) * 8) * 2);
    const uint32_t kRow  = (uint32_t)((lane & 7) + ((lane >> 4) << 3));
    const uint32_t kHalf = (uint32_t)(((lane >> 3) & 1) * 8);

    for (int c = 0; c < NCHUNK; c++) {
        if (c + 1 < NCHUNK) {
            load_chunk((c + 1) * BK, (c + 1) & 1);
            CP_WAIT(1);
        } else {
            CP_WAIT(0);
        }
        __syncthreads();

        const uint32_t sbase = sb + (c & 1) * STB;
        const uint32_t sA = sbase;
        const uint32_t sB = sbase + TBYTES;

#pragma unroll
        for (int ks = 0; ks < 4; ks++) {
            const uint32_t koff = (uint32_t)(ks * 16 * 2);
            uint32_t aH[4][4], bH[4][2];
#pragma unroll
            for (int mt = 0; mt < 4; mt++) {
                uint32_t ao = a_off + koff + (uint32_t)(mt * 16 * ROWH * 2);
                ldmx4(sA + ao, aH[mt][0], aH[mt][1], aH[mt][2], aH[mt][3]);
            }
#pragma unroll
            for (int ntp = 0; ntp < 2; ntp++) {
                uint32_t bo = (uint32_t)(((warp_n * 32 + ntp * 16 + kRow) * ROWH + ks * 16 + kHalf) * 2);
                ldmx4(sB + bo, bH[2 * ntp][0], bH[2 * ntp][1],
                               bH[2 * ntp + 1][0], bH[2 * ntp + 1][1]);
            }
#pragma unroll
            for (int mt = 0; mt < 4; mt++)
#pragma unroll
                for (int nt = 0; nt < 4; nt++)
                    mma_f16(acc[mt][nt], aH[mt], bH[nt]);
        }
        __syncthreads();
    }

    const int mb = m0 + warp_m * 64;
    const int nb = n0 + warp_n * 32;
#pragma unroll
    for (int mt = 0; mt < 4; mt++) {
#pragma unroll
        for (int nt = 0; nt < 4; nt++) {
            int r0 = mb + mt * 16 + (lane >> 2);
            int c0 = nb + nt * 8 + (lane & 3) * 2;
            if (MODE == 1) {
                *(float2*)(F + (size_t)r0 * D_MODEL + c0) =
                    make_float2(acc[mt][nt][0], acc[mt][nt][1]);
                *(float2*)(F + (size_t)(r0 + 8) * D_MODEL + c0) =
                    make_float2(acc[mt][nt][2], acc[mt][nt][3]);
            } else {
                __half* dst = (z == 0) ? Qo : (z == 1) ? Ko : Vo;
                *(__half2*)(dst + (size_t)r0 * D_MODEL + c0) =
                    __floats2half2_rn(acc[mt][nt][0], acc[mt][nt][1]);
                *(__half2*)(dst + (size_t)(r0 + 8) * D_MODEL + c0) =
                    __floats2half2_rn(acc[mt][nt][2], acc[mt][nt][3]);
            }
        }
    }
}

// ---------------------------------------------------------------------------
// fp16 flash attention (causal), max-free exp2 softmax, f16-acc S.
// Q loading uses its OWN cp.async group: waited once before the loop,
// fragments hoisted out (no per-iteration branch; Q ldmatrix overlaps KV0).
// ---------------------------------------------------------------------------
#define QT_B  (64 * 72 * 2)              // 9216
#define KVT_B (64 * 72 * 2)              // 9216
#define AT_SMEM (QT_B + 4 * KVT_B)       // 46080

__global__ void __launch_bounds__(128, 4)
attn3(const __half* __restrict__ Qp, const __half* __restrict__ Kp,
      const __half* __restrict__ Vp, __half* __restrict__ Oo)
{
    extern __shared__ char smem[];
    const uint32_t sb = smem_u32(smem);
    const int tid  = threadIdx.x;
    const int wid  = tid >> 5;         // 0..3
    const int lane = tid & 31;

    const int qt = (SEQ / 64 - 1) - blockIdx.x;   // descending
    const int h  = blockIdx.y;
    const int b  = blockIdx.z;
    const int q0 = qt * 64;
    const int ktmax = qt;

    const size_t gbase = ((size_t)b * SEQ) * D_MODEL + h * HD;

    // ---- load Q (64 rows) in its OWN commit group ----
#pragma unroll
    for (int j = 0; j < 4; j++) {
        int u = tid + j * 128;          // 0..511
        int row = u >> 3, ch = u & 7;
        uint32_t dst = sb + (uint32_t)((row * 72 + ch * 8) * 2);
        CP16(dst, Qp + gbase + (size_t)(q0 + row) * D_MODEL + ch * 8);
    }
    CP_COMMIT();

    const uint32_t kvbase = sb + QT_B;
    auto load_kv = [&](int kt, int stage) {
        const int k0 = kt * 64;
        const uint32_t sbase = kvbase + stage * 2 * KVT_B;
        const __half* src[2] = { Kp, Vp };
#pragma unroll
        for (int a = 0; a < 2; a++)
#pragma unroll
            for (int j = 0; j < 4; j++) {
                int u = tid + j * 128;
                int row = u >> 3, ch = u & 7;
                uint32_t dst = sbase + a * KVT_B + (uint32_t)((row * 72 + ch * 8) * 2);
                CP16(dst, src[a] + gbase + (size_t)(k0 + row) * D_MODEL + ch * 8);
            }
        CP_COMMIT();
    };

    load_kv(0, 0);
    if (ktmax >= 1) load_kv(1, 1);

    // ---- wait for Q only, hoist Q fragments out of the loop ----
    if (ktmax >= 1) { CP_WAIT(2); } else { CP_WAIT(1); }
    __syncthreads();
    uint32_t qh[4][4];
    {
        const uint32_t a_off = (uint32_t)(((wid * 16 + (lane & 15)) * 72 + (lane >> 4) * 8) * 2);
#pragma unroll
        for (int kc = 0; kc < 4; kc++) {
            uint32_t ao = a_off + (uint32_t)(kc * 16 * 2);
            ldmx4(sb + ao, qh[kc][0], qh[kc][1], qh[kc][2], qh[kc][3]);
        }
    }

    float l0 = 0.0f, l1 = 0.0f;
    float o[8][4];
#pragma unroll
    for (int nt = 0; nt < 8; nt++)
#pragma unroll
        for (int r = 0; r < 4; r++) o[nt][r] = 0.0f;

    const int rbase = q0 + wid * 16 + (lane >> 2);
    const __half2 row0h = __float2half2_rn((float)rbase);
    const __half2 row1h = __float2half2_rn((float)(rbase + 8));

    for (int kt = 0; kt <= ktmax; kt++) {
        if (kt + 1 <= ktmax) { CP_WAIT(1); } else { CP_WAIT(0); }
        __syncthreads();

        const int k0 = kt * 64;
        const bool active = (k0 <= q0 + wid * 16 + 15);

        if (active) {
            const uint32_t skv = kvbase + (kt & 1) * 2 * KVT_B;
            const uint32_t sK = skv, sV = skv + KVT_B;

            // ---- S = Q K^T, fp16 accumulate (packed output, no converts) ----
            uint32_t sh[8][2];
#pragma unroll
            for (int nt = 0; nt < 8; nt++) { sh[nt][0] = 0u; sh[nt][1] = 0u; }

            const uint32_t kRow = (uint32_t)((lane & 7) + ((lane >> 4) << 3));
            const uint32_t kHalf = (uint32_t)(((lane >> 3) & 1) * 8);
#pragma unroll
            for (int kc = 0; kc < 4; kc++) {
#pragma unroll
                for (int ntp = 0; ntp < 4; ntp++) {
                    uint32_t off = (uint32_t)(((ntp * 16 + kRow) * 72 + kc * 16 + kHalf) * 2);
                    uint32_t h0, h1, h2, h3;
                    ldmx4(sK + off, h0, h1, h2, h3);
                    uint32_t bHe[2] = { h0, h1 }, bHo[2] = { h2, h3 };
                    mma_f16acc(sh[2 * ntp],     qh[kc], bHe);
                    mma_f16acc(sh[2 * ntp + 1], qh[kc], bHo);
                }
            }

            // ---- P = exp2(S) directly on half2 ----
            __half2 e[8][2];
#pragma unroll
            for (int nt = 0; nt < 8; nt++) {
                e[nt][0] = h2exp2(*(__half2*)&sh[nt][0]);
                e[nt][1] = h2exp2(*(__half2*)&sh[nt][1]);
            }

            // ---- causal mask: multiply by 0/1 half2 (diagonal region only) ----
            if (k0 + 63 > q0 + wid * 16) {
                const int cb = k0 + (lane & 3) * 2;
#pragma unroll
                for (int nt = 0; nt < 8; nt++) {
                    float c0 = (float)(cb + nt * 8);
                    __half2 colh = __floats2half2_rn(c0, c0 + 1.0f);
                    e[nt][0] = __hmul2(e[nt][0], __hle2(colh, row0h));
                    e[nt][1] = __hmul2(e[nt][1], __hle2(colh, row1h));
                }
            }

            // ---- row sums: half2 tree + one promote per row-group ----
            {
                __half2 t0 = __hadd2(__hadd2(__hadd2(e[0][0], e[1][0]), __hadd2(e[2][0], e[3][0])),
                                     __hadd2(__hadd2(e[4][0], e[5][0]), __hadd2(e[6][0], e[7][0])));
                __half2 t1 = __hadd2(__hadd2(__hadd2(e[0][1], e[1][1]), __hadd2(e[2][1], e[3][1])),
                                     __hadd2(__hadd2(e[4][1], e[5][1]), __hadd2(e[6][1], e[7][1])));
                float2 f0 = __half22float2(t0), f1 = __half22float2(t1);
                l0 += f0.x + f0.y;
                l1 += f1.x + f1.y;
            }

            // ---- O += P V (fp32 accumulate) ----
            const uint32_t vKey = (uint32_t)((lane & 7) + (((lane >> 3) & 1) << 3));
            const uint32_t vDimSel = (uint32_t)((lane >> 4) * 8);
#pragma unroll
            for (int kc = 0; kc < 4; kc++) {
                uint32_t pa[4] = { *(uint32_t*)&e[2 * kc][0], *(uint32_t*)&e[2 * kc][1],
                                   *(uint32_t*)&e[2 * kc + 1][0], *(uint32_t*)&e[2 * kc + 1][1] };
#pragma unroll
                for (int ntp = 0; ntp < 4; ntp++) {
                    uint32_t off = (uint32_t)(((kc * 16 + vKey) * 72 + ntp * 16 + vDimSel) * 2);
                    uint32_t h0, h1, h2, h3;
                    ldmx4t(sV + off, h0, h1, h2, h3);
                    uint32_t bHe[2] = { h0, h1 }, bHo[2] = { h2, h3 };
                    mma_f16(o[2 * ntp],     pa, bHe);
                    mma_f16(o[2 * ntp + 1], pa, bHo);
                }
            }
        }

        __syncthreads();
        if (kt + 2 <= ktmax) load_kv(kt + 2, kt & 1);
    }

    // ---- epilogue: reduce row sums once, normalize, store fp16 ----
    l0 += __shfl_xor_sync(0xffffffffu, l0, 1);
    l0 += __shfl_xor_sync(0xffffffffu, l0, 2);
    l1 += __shfl_xor_sync(0xffffffffu, l1, 1);
    l1 += __shfl_xor_sync(0xffffffffu, l1, 2);
    const float inv0 = 1.0f / l0, inv1 = 1.0f / l1;
    const size_t orow0 = gbase + (size_t)(q0 + wid * 16 + (lane >> 2)) * D_MODEL + (lane & 3) * 2;
    const size_t orow1 = orow0 + 8 * D_MODEL;
#pragma unroll
    for (int nt = 0; nt < 8; nt++) {
        *(__half2*)(Oo + orow0 + nt * 8) =
            __floats2half2_rn(o[nt][0] * inv0, o[nt][1] * inv0);
        *(__half2*)(Oo + orow1 + nt * 8) =
            __floats2half2_rn(o[nt][2] * inv1, o[nt][3] * inv1);
    }
}

// ---------------------------------------------------------------------------
extern "C" void kernel_launch(void* const* d_in, const int* in_sizes, int n_in,
                              void* d_out, int out_size)
{
    const float* x  = (const float*)d_in[0];
    float* out = (float*)d_out;

    __half *xh, *w, *q, *k, *v, *a;
    cudaGetSymbolAddress((void**)&xh, g_x);
    cudaGetSymbolAddress((void**)&w,  g_w);
    cudaGetSymbolAddress((void**)&q,  g_q);
    cudaGetSymbolAddress((void**)&k,  g_k);
    cudaGetSymbolAddress((void**)&v,  g_v);
    cudaGetSymbolAddress((void**)&a,  g_a);

    // one prep launch, exact-sized grid
    prep_all<<<PREP_BLOCKS, 256>>>((const float2*)x,
                                   (const float2*)d_in[1], (const float2*)d_in[2],
                                   (const float2*)d_in[3], (const float2*)d_in[4],
                                   (__half2*)xh, (__half2*)w);

    cudaFuncSetAttribute(gemm2<0>, cudaFuncAttributeMaxDynamicSharedMemorySize, GSMEM);
    cudaFuncSetAttribute(gemm2<1>, cudaFuncAttributeMaxDynamicSharedMemorySize, GSMEM);

    dim3 gq(D_MODEL / BN, MTOT / BM, 3);
    gemm2<0><<<gq, 256, GSMEM>>>(xh, w, q, k, v, nullptr);

    cudaFuncSetAttribute(attn3, cudaFuncAttributeMaxDynamicSharedMemorySize, AT_SMEM);
    dim3 ga(SEQ / 64, NH, BATCH);
    attn3<<<ga, 128, AT_SMEM>>>(q, k, v, a);

    dim3 go(D_MODEL / BN, MTOT / BM, 1);
    gemm2<1><<<go, 256, GSMEM>>>(a, w + 3 * (size_t)D_MODEL * D_MODEL,
                                 nullptr, nullptr, nullptr, out);
}